// round 3
// baseline (speedup 1.0000x reference)
#include <cuda_runtime.h>
#include <math.h>
#include <stdint.h>

// Problem constants
#define TT   256
#define BB   64
#define EE   512
#define HDD  256
#define NGG  1024         // 4*HD
#define KK   7
#define START_TAG 5
#define STOP_TAG  6
#define NEGV (-10000.0f)
#define RR   (TT*BB)      // 16384 rows

// ---------------- scratch (static device memory; no allocation) ----------------
__device__ float g_xg[2u * NGG * RR];       // [2048][16384] gate-major input gates
__device__ float g_xmid[(size_t)RR * 512];  // layer-0 output (concat hf|hb)
__device__ float g_xout[(size_t)RR * 512];  // layer-1 output
__device__ float g_h[4 * BB * HDD];         // [dir*2 + parity][64*256] h exchange
__device__ float g_feats[RR * KK];
__device__ unsigned char g_bp[TT * BB * 8];
__device__ unsigned int g_barcnt[2];        // monotonic, never reset
__device__ unsigned int g_barflag[2];       // monotonic, never reset

// tf32 3-split scratch
__device__ float g_ahi[2048 * 512];         // w_ih[layer] hi (tf32 bits in fp32 slots)
__device__ float g_alo[2048 * 512];         // w_ih[layer] lo
__device__ float g_bhi[(size_t)RR * 512];   // x rows hi
__device__ float g_blo[(size_t)RR * 512];   // x rows lo

// ---------------------------------------------------------------------------------
__device__ __forceinline__ void tf32split(float v, uint32_t& hi, uint32_t& lo) {
    asm("cvt.rna.tf32.f32 %0, %1;" : "=r"(hi) : "f"(v));
    float l = v - __uint_as_float(hi);
    asm("cvt.rna.tf32.f32 %0, %1;" : "=r"(lo) : "f"(l));
}

__device__ __forceinline__ void mma8(float* c,
    uint32_t a0, uint32_t a1, uint32_t a2, uint32_t a3,
    uint32_t b0, uint32_t b1)
{
    asm volatile(
        "mma.sync.aligned.m16n8k8.row.col.f32.tf32.tf32.f32 "
        "{%0,%1,%2,%3},{%4,%5,%6,%7},{%8,%9},{%0,%1,%2,%3};"
        : "+f"(c[0]), "+f"(c[1]), "+f"(c[2]), "+f"(c[3])
        : "r"(a0), "r"(a1), "r"(a2), "r"(a3), "r"(b0), "r"(b1));
}

__device__ __forceinline__ void cpasync16(uint32_t s, const void* g) {
    asm volatile("cp.async.cg.shared.global [%0], [%1], 16;\n" :: "r"(s), "l"(g));
}
__device__ __forceinline__ void cpcommit() { asm volatile("cp.async.commit_group;\n"); }
template<int N> __device__ __forceinline__ void cpwait() {
    asm volatile("cp.async.wait_group %0;\n" :: "n"(N));
}

// =================================================================================
// split kernels: precompute tf32 hi/lo decompositions into global scratch
// =================================================================================
__global__ void split_w(int layer, const float* __restrict__ w_ih)
{
    int idx = blockIdx.x * 256 + threadIdx.x;          // float4 index, 262144 total
    float4 v = ((const float4*)(w_ih + (size_t)layer * 2048 * 512))[idx];
    uint32_t h0,l0,h1,l1,h2,l2,h3,l3;
    tf32split(v.x, h0, l0); tf32split(v.y, h1, l1);
    tf32split(v.z, h2, l2); tf32split(v.w, h3, l3);
    float4 hv = { __uint_as_float(h0), __uint_as_float(h1), __uint_as_float(h2), __uint_as_float(h3) };
    float4 lv = { __uint_as_float(l0), __uint_as_float(l1), __uint_as_float(l2), __uint_as_float(l3) };
    ((float4*)g_ahi)[idx] = hv;
    ((float4*)g_alo)[idx] = lv;
}

__global__ void split_x(int mode, const int* __restrict__ sent,
                        const float* __restrict__ emb)
{
    int r = blockIdx.x;                                 // 0..16383
    int t = threadIdx.x;                                // 0..127
    const float* src = mode ? (g_xmid + (size_t)r * 512)
                            : (emb + (size_t)sent[r] * 512);
    float4 v = ((const float4*)src)[t];
    uint32_t h0,l0,h1,l1,h2,l2,h3,l3;
    tf32split(v.x, h0, l0); tf32split(v.y, h1, l1);
    tf32split(v.z, h2, l2); tf32split(v.w, h3, l3);
    float4 hv = { __uint_as_float(h0), __uint_as_float(h1), __uint_as_float(h2), __uint_as_float(h3) };
    float4 lv = { __uint_as_float(l0), __uint_as_float(l1), __uint_as_float(l2), __uint_as_float(l3) };
    ((float4*)(g_bhi + (size_t)r * 512))[t] = hv;
    ((float4*)(g_blo + (size_t)r * 512))[t] = lv;
}

// =================================================================================
// Tensor-core GEMM (3xTF32): xg[m][n] = bias[m] + sum_k w[m][k]*x[n][k]
// Block 128x128, K chunks of 32, 128 threads = 4 warps (2x2), warp tile 64x64.
// Smem tiles [row][36] (bank-conflict-free frag loads), cp.async double-buffered.
// =================================================================================
#define GBK 32
#define GAS 36
#define GTILE (128 * GAS)                   // floats per tile
#define GBUF (4 * GTILE)                    // Ahi,Alo,Bhi,Blo

__global__ void __launch_bounds__(128, 1) gemm_tc(
    const float* __restrict__ bihL,         // already layer-offset
    const float* __restrict__ bhhL)
{
    extern __shared__ float sm[];
    const int tid  = threadIdx.x;
    const int lane = tid & 31;
    const int w    = tid >> 5;
    const int wm   = w >> 1, wn = w & 1;
    const int gid  = lane >> 2, tg = lane & 3;
    const int m0   = blockIdx.x * 128;
    const int n0   = blockIdx.y * 128;

    const float* gah = g_ahi + (size_t)(m0 + tid) * 512;
    const float* gal = g_alo + (size_t)(m0 + tid) * 512;
    const float* gbh = g_bhi + (size_t)(n0 + tid) * 512;
    const float* gbl = g_blo + (size_t)(n0 + tid) * 512;

    float acc[4][8][4];
#pragma unroll
    for (int mf = 0; mf < 4; mf++)
#pragma unroll
        for (int nf = 0; nf < 8; nf++)
#pragma unroll
            for (int i = 0; i < 4; i++) acc[mf][nf][i] = 0.f;

    // stage chunk kc into buffer buf
    auto stage = [&](int kc, int buf) {
        float* base = sm + buf * GBUF;
        uint32_t sA = (uint32_t)__cvta_generic_to_shared(base + tid * GAS);
#pragma unroll
        for (int i = 0; i < 8; i++) cpasync16(sA + i * 16, gah + kc + i * 4);
        sA += GTILE * 4;                     // bytes? careful: addresses in bytes
#pragma unroll
        for (int i = 0; i < 8; i++) cpasync16(sA + i * 16, gal + kc + i * 4);
        sA += GTILE * 4;
#pragma unroll
        for (int i = 0; i < 8; i++) cpasync16(sA + i * 16, gbh + kc + i * 4);
        sA += GTILE * 4;
#pragma unroll
        for (int i = 0; i < 8; i++) cpasync16(sA + i * 16, gbl + kc + i * 4);
    };

    stage(0, 0);
    cpcommit();

    const int NC = 512 / GBK;               // 16 chunks
    for (int c = 0; c < NC; c++) {
        if (c + 1 < NC) { stage((c + 1) * GBK, (c + 1) & 1); cpcommit(); cpwait<1>(); }
        else           { cpwait<0>(); }
        __syncthreads();

        float* buf = sm + (c & 1) * GBUF;
        const float* Ah = buf;
        const float* Al = buf + GTILE;
        const float* Bh = buf + 2 * GTILE;
        const float* Bl = buf + 3 * GTILE;

#pragma unroll
        for (int kk = 0; kk < GBK; kk += 8) {
            uint32_t bh0[8], bh1[8], bl0[8], bl1[8];
#pragma unroll
            for (int nf = 0; nf < 8; nf++) {
                int rB = (wn * 64 + nf * 8 + gid) * GAS + kk + tg;
                bh0[nf] = __float_as_uint(Bh[rB]);
                bh1[nf] = __float_as_uint(Bh[rB + 4]);
                bl0[nf] = __float_as_uint(Bl[rB]);
                bl1[nf] = __float_as_uint(Bl[rB + 4]);
            }
#pragma unroll
            for (int mf = 0; mf < 4; mf++) {
                int rA = (wm * 64 + mf * 16 + gid) * GAS + kk + tg;
                uint32_t ah0 = __float_as_uint(Ah[rA]);
                uint32_t ah1 = __float_as_uint(Ah[rA + 8 * GAS]);
                uint32_t ah2 = __float_as_uint(Ah[rA + 4]);
                uint32_t ah3 = __float_as_uint(Ah[rA + 8 * GAS + 4]);
                uint32_t al0 = __float_as_uint(Al[rA]);
                uint32_t al1 = __float_as_uint(Al[rA + 8 * GAS]);
                uint32_t al2 = __float_as_uint(Al[rA + 4]);
                uint32_t al3 = __float_as_uint(Al[rA + 8 * GAS + 4]);
#pragma unroll
                for (int nf = 0; nf < 8; nf++) {
                    mma8(acc[mf][nf], ah0, ah1, ah2, ah3, bh0[nf], bh1[nf]);
                    mma8(acc[mf][nf], ah0, ah1, ah2, ah3, bl0[nf], bl1[nf]);
                    mma8(acc[mf][nf], al0, al1, al2, al3, bh0[nf], bh1[nf]);
                }
            }
        }
        __syncthreads();
    }

    // epilogue: bias + store gate-major
#pragma unroll
    for (int mf = 0; mf < 4; mf++) {
        int m  = m0 + wm * 64 + mf * 16 + gid;
        float bias0 = __ldg(&bihL[m])     + __ldg(&bhhL[m]);
        float bias8 = __ldg(&bihL[m + 8]) + __ldg(&bhhL[m + 8]);
#pragma unroll
        for (int nf = 0; nf < 8; nf++) {
            int n = n0 + wn * 64 + nf * 8 + 2 * tg;
            float2 v0 = { acc[mf][nf][0] + bias0, acc[mf][nf][1] + bias0 };
            float2 v1 = { acc[mf][nf][2] + bias8, acc[mf][nf][3] + bias8 };
            *(float2*)(g_xg + (size_t)m * RR + n)       = v0;
            *(float2*)(g_xg + (size_t)(m + 8) * RR + n) = v1;
        }
    }
}

// =================================================================================
// Persistent bidirectional LSTM layer (unchanged from round 1).
// =================================================================================
__global__ void __launch_bounds__(256) lstm_layer(
    int layer,
    const float* __restrict__ w_hh,
    const float* __restrict__ h0,
    const float* __restrict__ c0)
{
    extern __shared__ float sm[];
    float* h_s = sm;               // [64][260] padded
    float* w_s = sm + 64 * 260;    // [16][256] : row = q*4 + jl

    const int d   = blockIdx.y;
    const int j0  = blockIdx.x * 4;
    const int tid = threadIdx.x;
    const int b   = tid & 63;
    const int jl  = tid >> 6;
    const int col = j0 + jl;

    float* out_x = layer ? g_xout : g_xmid;
    const float* xg = g_xg + (size_t)d * NGG * RR;

    const float* wl = w_hh + (size_t)(layer*2 + d) * 1024 * 256;
    for (int idx = tid; idx < 16*256; idx += 256) {
        int rr = idx >> 8, k = idx & 255;
        int q = rr >> 2, jj = rr & 3;
        w_s[rr*256 + k] = wl[(size_t)(q*256 + j0 + jj)*256 + k];
    }

    float c = c0[(2*layer + d) * (BB*HDD) + b*HDD + col];

    unsigned fbase = 0;
    if (tid == 0) fbase = atomicAdd(&g_barflag[d], 0u);

    for (int s = 0; s < TT; ++s) {
        int te  = d ? (TT - 1 - s) : s;
        int row = te * BB + b;

        const float* hsrc = (s == 0) ? (h0 + (2*layer + d) * (BB*HDD))
                                     : (g_h + (size_t)(d*2 + ((s+1)&1)) * (BB*HDD));
        for (int i = tid; i < 4096; i += 256) {
            float4 v = __ldcg(((const float4*)hsrc) + i);
            int fi = i * 4;
            *(float4*)(h_s + (fi >> 8) * 260 + (fi & 255)) = v;
        }
        float xgi = __ldg(&xg[(size_t)(0*256 + col) * RR + row]);
        float xgf = __ldg(&xg[(size_t)(1*256 + col) * RR + row]);
        float xgg = __ldg(&xg[(size_t)(2*256 + col) * RR + row]);
        float xgo = __ldg(&xg[(size_t)(3*256 + col) * RR + row]);
        __syncthreads();

        float a0 = 0.f, a1 = 0.f, a2 = 0.f, a3 = 0.f;
        const float* hp = h_s + b * 260;
        const float* w0 = w_s + (0*4 + jl) * 256;
        const float* w1 = w_s + (1*4 + jl) * 256;
        const float* w2 = w_s + (2*4 + jl) * 256;
        const float* w3 = w_s + (3*4 + jl) * 256;
#pragma unroll 8
        for (int k = 0; k < 256; k += 4) {
            float4 hv = *(const float4*)(hp + k);
            float4 v0 = *(const float4*)(w0 + k);
            float4 v1 = *(const float4*)(w1 + k);
            float4 v2 = *(const float4*)(w2 + k);
            float4 v3 = *(const float4*)(w3 + k);
            a0 += hv.x*v0.x + hv.y*v0.y + hv.z*v0.z + hv.w*v0.w;
            a1 += hv.x*v1.x + hv.y*v1.y + hv.z*v1.z + hv.w*v1.w;
            a2 += hv.x*v2.x + hv.y*v2.y + hv.z*v2.z + hv.w*v2.w;
            a3 += hv.x*v3.x + hv.y*v3.y + hv.z*v3.z + hv.w*v3.w;
        }

        float gi = 1.f / (1.f + expf(-(xgi + a0)));
        float gf = 1.f / (1.f + expf(-(xgf + a1)));
        float gg = tanhf(xgg + a2);
        float go = 1.f / (1.f + expf(-(xgo + a3)));
        c = gf * c + gi * gg;
        float h = go * tanhf(c);

        g_h[(size_t)(d*2 + (s & 1)) * (BB*HDD) + b*HDD + col] = h;
        out_x[(size_t)row * 512 + d*256 + col] = h;

        if (s < TT - 1) {
            __threadfence();
            __syncthreads();
            if (tid == 0) {
                unsigned v = atomicAdd(&g_barcnt[d], 1u);
                if ((v & 63u) == 63u)
                    atomicExch(&g_barflag[d], fbase + (unsigned)(s + 1));
                unsigned tgt = (unsigned)(s + 1);
                while ((unsigned)(atomicAdd(&g_barflag[d], 0u) - fbase) < tgt)
                    __nanosleep(32);
            }
            __syncthreads();
        }
    }
}

// =================================================================================
__global__ void feats_kernel(const float* __restrict__ wout,
                             const float* __restrict__ bout)
{
    int r = blockIdx.x;
    int w = threadIdx.x >> 5;
    int lane = threadIdx.x & 31;
    const float* xr = g_xout + (size_t)r * 512;
    const float* wr = wout + w * 512;
    float acc = 0.f;
#pragma unroll
    for (int i = 0; i < 16; i++) {
        int e = lane + i * 32;
        acc += xr[e] * wr[e];
    }
#pragma unroll
    for (int o = 16; o; o >>= 1) acc += __shfl_down_sync(0xffffffffu, acc, o);
    if (lane == 0) g_feats[r * KK + w] = acc + bout[w];
}

// =================================================================================
__global__ void viterbi_kernel(const float* __restrict__ trans,
                               void* out, int floatmode)
{
    __shared__ float vbuf[2][64][8];
    __shared__ float tr[7][7];

    int tid = threadIdx.x;
    if (tid < 49) tr[tid / 7][tid % 7] = trans[tid];
    int b  = tid & 63;
    int nx = tid >> 6;
    vbuf[0][b][nx] = (nx == START_TAG) ? 0.f : NEGV;
    __syncthreads();

    int p = 0;
    for (int t = 0; t < TT; ++t) {
        float best = vbuf[p][b][0] + tr[nx][0];
        int   bp   = 0;
#pragma unroll
        for (int pv = 1; pv < 7; ++pv) {
            float cnd = vbuf[p][b][pv] + tr[nx][pv];
            if (cnd > best) { best = cnd; bp = pv; }
        }
        vbuf[p ^ 1][b][nx] = best + g_feats[(t*BB + b) * KK + nx];
        g_bp[(t*BB + b) * 8 + nx] = (unsigned char)bp;
        __syncthreads();
        p ^= 1;
    }

    if (tid < 64) {
        float bestt = vbuf[p][tid][0] + tr[STOP_TAG][0];
        int   lastt = 0;
#pragma unroll
        for (int k2 = 1; k2 < 7; ++k2) {
            float cnd = vbuf[p][tid][k2] + tr[STOP_TAG][k2];
            if (cnd > bestt) { bestt = cnd; lastt = k2; }
        }
        int tag = lastt;
        if (floatmode) {
            float* fo = (float*)out;
            fo[RR + tid] = bestt;
            for (int t = TT - 1; t >= 0; --t) {
                fo[tid * TT + t] = (float)tag;
                tag = g_bp[(t*BB + tid) * 8 + tag];
            }
        } else {
            int* io = (int*)out;
            for (int t = TT - 1; t >= 0; --t) {
                io[tid * TT + t] = tag;
                tag = g_bp[(t*BB + tid) * 8 + tag];
            }
        }
    }
}

// =================================================================================
extern "C" void kernel_launch(void* const* d_in, const int* in_sizes, int n_in,
                              void* d_out, int out_size)
{
    const int*   sent  = (const int*)  d_in[0];
    const float* emb   = (const float*)d_in[1];
    const float* w_ih  = (const float*)d_in[2];
    const float* w_hh  = (const float*)d_in[3];
    const float* b_ih  = (const float*)d_in[4];
    const float* b_hh  = (const float*)d_in[5];
    const float* w_out = (const float*)d_in[6];
    const float* b_out = (const float*)d_in[7];
    const float* trans = (const float*)d_in[8];
    const float* h0    = (const float*)d_in[9];
    const float* c0    = (const float*)d_in[10];

    size_t lsmem = (size_t)(64*260 + 16*256) * sizeof(float);
    cudaFuncSetAttribute(lstm_layer, cudaFuncAttributeMaxDynamicSharedMemorySize, (int)lsmem);
    size_t gsmem = (size_t)2 * GBUF * sizeof(float);      // 147456 B
    cudaFuncSetAttribute(gemm_tc, cudaFuncAttributeMaxDynamicSharedMemorySize, (int)gsmem);

    dim3 ggrid(16, 128);          // x = m-tiles (share B tile in L2), y = n-tiles
    dim3 lgrid(64, 2);

    // layer 0
    split_w<<<1024, 256>>>(0, w_ih);
    split_x<<<RR, 128>>>(0, sent, emb);
    gemm_tc<<<ggrid, 128, gsmem>>>(b_ih + 0 * 2048, b_hh + 0 * 2048);
    lstm_layer<<<lgrid, 256, lsmem>>>(0, w_hh, h0, c0);
    // layer 1
    split_w<<<1024, 256>>>(1, w_ih);
    split_x<<<RR, 128>>>(1, sent, emb);
    gemm_tc<<<ggrid, 128, gsmem>>>(b_ih + 1 * 2048, b_hh + 1 * 2048);
    lstm_layer<<<lgrid, 256, lsmem>>>(1, w_hh, h0, c0);

    feats_kernel<<<RR, 224>>>(w_out, b_out);

    int floatmode = (out_size == RR + BB) ? 1 : 0;
    viterbi_kernel<<<1, 448>>>(trans, d_out, floatmode);
}

// round 4
// speedup vs baseline: 1.1041x; 1.1041x over previous
#include <cuda_runtime.h>
#include <math.h>

// Problem constants
#define TT   256
#define BB   64
#define EE   512
#define HDD  256
#define NGG  1024         // 4*HD
#define KK   7
#define START_TAG 5
#define STOP_TAG  6
#define NEGV (-10000.0f)
#define RR   (TT*BB)      // 16384 rows

// ---------------- scratch (static device memory; no allocation) ----------------
__device__ float g_xg[2u * NGG * RR];       // [2048][16384] gate-major input gates
__device__ float g_xmid[(size_t)RR * 512];  // layer-0 output (concat hf|hb)
__device__ float g_xout[(size_t)RR * 512];  // layer-1 output
__device__ float g_h[4 * BB * HDD];         // [dir*2 + parity][64*256] h exchange
__device__ float g_feats[RR * KK];
__device__ unsigned char g_bp[TT * BB * 8];
__device__ unsigned int g_flags[2][64 * 8]; // per-CTA step flags, one per 32B sector

// =================================================================================
// zero all flags at the start of every launch (graph-replay safe)
// =================================================================================
__global__ void reset_flags()
{
    int t = threadIdx.x;
    if (t < 128) g_flags[t >> 6][(t & 63) * 8] = 0u;
}

// =================================================================================
// fp32 GEMM (round-1 version, measured faster than tc path):
// xg[m][r] = bias[m] + sum_k A[m][k] * X[r][k], gate-major output.
// Tiles 128x128x16, 8x8 microtile, 256 threads.
// =================================================================================
__global__ void __launch_bounds__(256) gemm_xg(
    int layer,
    const int*   __restrict__ sent,
    const float* __restrict__ emb,
    const float* __restrict__ w_ih,
    const float* __restrict__ b_ih,
    const float* __restrict__ b_hh)
{
    __shared__ float As[16][132];
    __shared__ float Bs[16][132];

    const float* A    = w_ih + (size_t)layer * 2 * 1024 * 512;
    const float* bihL = b_ih + layer * 2048;
    const float* bhhL = b_hh + layer * 2048;
    const float* Bsrc;
    const int*   sidx;
    if (layer == 0) { Bsrc = emb;    sidx = sent; }
    else            { Bsrc = g_xmid; sidx = 0;    }

    int tid = threadIdx.x;
    int n0 = blockIdx.x * 128;
    int m0 = blockIdx.y * 128;
    int tx = tid & 15, ty = tid >> 4;

    int ar0 = tid >> 2;
    int ac0 = (tid & 3) * 4;

    int rn0 = n0 + ar0;
    int rn1 = n0 + ar0 + 64;
    const float* brow0 = Bsrc + (size_t)(sidx ? sidx[rn0] : rn0) * 512 + ac0;
    const float* brow1 = Bsrc + (size_t)(sidx ? sidx[rn1] : rn1) * 512 + ac0;
    const float* arow0 = A + (size_t)(m0 + ar0)      * 512 + ac0;
    const float* arow1 = A + (size_t)(m0 + ar0 + 64) * 512 + ac0;

    float acc[8][8];
#pragma unroll
    for (int i = 0; i < 8; i++)
#pragma unroll
        for (int j = 0; j < 8; j++) acc[i][j] = 0.f;

    for (int k0 = 0; k0 < 512; k0 += 16) {
        float4 a0 = *(const float4*)(arow0 + k0);
        float4 a1 = *(const float4*)(arow1 + k0);
        float4 b0 = *(const float4*)(brow0 + k0);
        float4 b1 = *(const float4*)(brow1 + k0);
        __syncthreads();
        As[ac0+0][ar0]    = a0.x; As[ac0+1][ar0]    = a0.y; As[ac0+2][ar0]    = a0.z; As[ac0+3][ar0]    = a0.w;
        As[ac0+0][ar0+64] = a1.x; As[ac0+1][ar0+64] = a1.y; As[ac0+2][ar0+64] = a1.z; As[ac0+3][ar0+64] = a1.w;
        Bs[ac0+0][ar0]    = b0.x; Bs[ac0+1][ar0]    = b0.y; Bs[ac0+2][ar0]    = b0.z; Bs[ac0+3][ar0]    = b0.w;
        Bs[ac0+0][ar0+64] = b1.x; Bs[ac0+1][ar0+64] = b1.y; Bs[ac0+2][ar0+64] = b1.z; Bs[ac0+3][ar0+64] = b1.w;
        __syncthreads();
#pragma unroll
        for (int kk = 0; kk < 16; kk++) {
            float a[8], b[8];
#pragma unroll
            for (int i = 0; i < 8; i++) a[i] = As[kk][ty*8 + i];
#pragma unroll
            for (int j = 0; j < 8; j++) b[j] = Bs[kk][tx*8 + j];
#pragma unroll
            for (int i = 0; i < 8; i++)
#pragma unroll
                for (int j = 0; j < 8; j++) acc[i][j] += a[i] * b[j];
        }
    }

#pragma unroll
    for (int i = 0; i < 8; i++) {
        int m = m0 + ty*8 + i;
        float bias = __ldg(&bihL[m]) + __ldg(&bhhL[m]);
        float* outp = g_xg + (size_t)m * RR + n0 + tx*8;
#pragma unroll
        for (int j = 0; j < 8; j++) outp[j] = acc[i][j] + bias;
    }
}

// =================================================================================
// Persistent bidirectional LSTM layer. Grid (64, 2): blockIdx.y = direction.
// Per-CTA produce-flags replace the central atomic barrier:
//   producer: h store -> threadfence -> st.cg flag = base+s+1 (own 32B sector)
//   consumer: 64 threads poll 64 flags with ld.cg until >= base+s, syncthreads,
//             then load h (parity (s+1)&1).
// Flags are monotone within a launch (layer 0: 1..256, layer 1: 257..512) and
// zeroed by reset_flags at the top of every launch.
// =================================================================================
__global__ void __launch_bounds__(256) lstm_layer(
    int layer,
    const float* __restrict__ w_hh,
    const float* __restrict__ h0,
    const float* __restrict__ c0)
{
    extern __shared__ float sm[];
    float* h_s = sm;               // [64][260] padded
    float* w_s = sm + 64 * 260;    // [16][256] : row = q*4 + jl

    const int d   = blockIdx.y;
    const int cta = blockIdx.x;    // 0..63
    const int j0  = cta * 4;
    const int tid = threadIdx.x;
    const int b   = tid & 63;
    const int jl  = tid >> 6;
    const int col = j0 + jl;

    const unsigned base = (unsigned)layer * (unsigned)TT;

    float* out_x = layer ? g_xout : g_xmid;
    const float* xg = g_xg + (size_t)d * NGG * RR;

    // stage this CTA's 16 W_hh rows into SMEM
    const float* wl = w_hh + (size_t)(layer*2 + d) * 1024 * 256;
    for (int idx = tid; idx < 16*256; idx += 256) {
        int rr = idx >> 8, k = idx & 255;
        int q = rr >> 2, jj = rr & 3;
        w_s[rr*256 + k] = wl[(size_t)(q*256 + j0 + jj)*256 + k];
    }

    float c = c0[(2*layer + d) * (BB*HDD) + b*HDD + col];

    unsigned* myflag   = &g_flags[d][cta * 8];
    unsigned* pollflag = &g_flags[d][(tid & 63) * 8];

    for (int s = 0; s < TT; ++s) {
        int te  = d ? (TT - 1 - s) : s;
        int row = te * BB + b;

        // prefetch input gates (independent of the flag wait)
        float xgi = __ldg(&xg[(size_t)(0*256 + col) * RR + row]);
        float xgf = __ldg(&xg[(size_t)(1*256 + col) * RR + row]);
        float xgg = __ldg(&xg[(size_t)(2*256 + col) * RR + row]);
        float xgo = __ldg(&xg[(size_t)(3*256 + col) * RR + row]);

        // wait for all 64 producer flags from step s-1
        if (s > 0 && tid < 64) {
            unsigned tgt = base + (unsigned)s;
            unsigned v;
            do {
                asm volatile("ld.global.cg.u32 %0, [%1];" : "=r"(v) : "l"(pollflag));
            } while (v < tgt);
        }
        __syncthreads();   // poll done; also protects h_s reuse from previous step

        const float* hsrc = (s == 0) ? (h0 + (2*layer + d) * (BB*HDD))
                                     : (g_h + (size_t)(d*2 + ((s+1)&1)) * (BB*HDD));
        for (int i = tid; i < 4096; i += 256) {
            float4 v = __ldcg(((const float4*)hsrc) + i);
            int fi = i * 4;
            *(float4*)(h_s + (fi >> 8) * 260 + (fi & 255)) = v;
        }
        __syncthreads();

        float a0 = 0.f, a1 = 0.f, a2 = 0.f, a3 = 0.f;
        const float* hp = h_s + b * 260;
        const float* w0 = w_s + (0*4 + jl) * 256;
        const float* w1 = w_s + (1*4 + jl) * 256;
        const float* w2 = w_s + (2*4 + jl) * 256;
        const float* w3 = w_s + (3*4 + jl) * 256;
#pragma unroll 8
        for (int k = 0; k < 256; k += 4) {
            float4 hv = *(const float4*)(hp + k);
            float4 v0 = *(const float4*)(w0 + k);
            float4 v1 = *(const float4*)(w1 + k);
            float4 v2 = *(const float4*)(w2 + k);
            float4 v3 = *(const float4*)(w3 + k);
            a0 += hv.x*v0.x + hv.y*v0.y + hv.z*v0.z + hv.w*v0.w;
            a1 += hv.x*v1.x + hv.y*v1.y + hv.z*v1.z + hv.w*v1.w;
            a2 += hv.x*v2.x + hv.y*v2.y + hv.z*v2.z + hv.w*v2.w;
            a3 += hv.x*v3.x + hv.y*v3.y + hv.z*v3.z + hv.w*v3.w;
        }

        float gi = 1.f / (1.f + expf(-(xgi + a0)));
        float gf = 1.f / (1.f + expf(-(xgf + a1)));
        float gg = tanhf(xgg + a2);
        float go = 1.f / (1.f + expf(-(xgo + a3)));
        c = gf * c + gi * gg;
        float h = go * tanhf(c);

        g_h[(size_t)(d*2 + (s & 1)) * (BB*HDD) + b*HDD + col] = h;
        out_x[(size_t)row * 512 + d*256 + col] = h;

        // publish: make h visible, then raise this CTA's flag (no atomics)
        __threadfence();
        __syncthreads();
        if (tid == 0) {
            unsigned v = base + (unsigned)(s + 1);
            asm volatile("st.global.cg.u32 [%0], %1;" :: "l"(myflag), "r"(v));
        }
    }
}

// =================================================================================
// feats[r][k] = b_out[k] + dot(x2[r], w_out[k]); one warp per tag, 7 warps/row
// =================================================================================
__global__ void feats_kernel(const float* __restrict__ wout,
                             const float* __restrict__ bout)
{
    int r = blockIdx.x;
    int w = threadIdx.x >> 5;
    int lane = threadIdx.x & 31;
    const float* xr = g_xout + (size_t)r * 512;
    const float* wr = wout + w * 512;
    float acc = 0.f;
#pragma unroll
    for (int i = 0; i < 16; i++) {
        int e = lane + i * 32;
        acc += xr[e] * wr[e];
    }
#pragma unroll
    for (int o = 16; o; o >>= 1) acc += __shfl_down_sync(0xffffffffu, acc, o);
    if (lane == 0) g_feats[r * KK + w] = acc + bout[w];
}

// =================================================================================
// Viterbi: 448 threads = 64 batch x 7 next-tags
// =================================================================================
__global__ void viterbi_kernel(const float* __restrict__ trans,
                               void* out, int floatmode)
{
    __shared__ float vbuf[2][64][8];
    __shared__ float tr[7][7];

    int tid = threadIdx.x;
    if (tid < 49) tr[tid / 7][tid % 7] = trans[tid];
    int b  = tid & 63;
    int nx = tid >> 6;
    vbuf[0][b][nx] = (nx == START_TAG) ? 0.f : NEGV;
    __syncthreads();

    int p = 0;
    for (int t = 0; t < TT; ++t) {
        float best = vbuf[p][b][0] + tr[nx][0];
        int   bp   = 0;
#pragma unroll
        for (int pv = 1; pv < 7; ++pv) {
            float cnd = vbuf[p][b][pv] + tr[nx][pv];
            if (cnd > best) { best = cnd; bp = pv; }
        }
        vbuf[p ^ 1][b][nx] = best + g_feats[(t*BB + b) * KK + nx];
        g_bp[(t*BB + b) * 8 + nx] = (unsigned char)bp;
        __syncthreads();
        p ^= 1;
    }

    if (tid < 64) {
        float bestt = vbuf[p][tid][0] + tr[STOP_TAG][0];
        int   lastt = 0;
#pragma unroll
        for (int k2 = 1; k2 < 7; ++k2) {
            float cnd = vbuf[p][tid][k2] + tr[STOP_TAG][k2];
            if (cnd > bestt) { bestt = cnd; lastt = k2; }
        }
        int tag = lastt;
        if (floatmode) {
            float* fo = (float*)out;
            fo[RR + tid] = bestt;
            for (int t = TT - 1; t >= 0; --t) {
                fo[tid * TT + t] = (float)tag;
                tag = g_bp[(t*BB + tid) * 8 + tag];
            }
        } else {
            int* io = (int*)out;
            for (int t = TT - 1; t >= 0; --t) {
                io[tid * TT + t] = tag;
                tag = g_bp[(t*BB + tid) * 8 + tag];
            }
        }
    }
}

// =================================================================================
extern "C" void kernel_launch(void* const* d_in, const int* in_sizes, int n_in,
                              void* d_out, int out_size)
{
    const int*   sent  = (const int*)  d_in[0];
    const float* emb   = (const float*)d_in[1];
    const float* w_ih  = (const float*)d_in[2];
    const float* w_hh  = (const float*)d_in[3];
    const float* b_ih  = (const float*)d_in[4];
    const float* b_hh  = (const float*)d_in[5];
    const float* w_out = (const float*)d_in[6];
    const float* b_out = (const float*)d_in[7];
    const float* trans = (const float*)d_in[8];
    const float* h0    = (const float*)d_in[9];
    const float* c0    = (const float*)d_in[10];

    size_t lsmem = (size_t)(64*260 + 16*256) * sizeof(float);   // ~83 KB
    cudaFuncSetAttribute(lstm_layer, cudaFuncAttributeMaxDynamicSharedMemorySize, (int)lsmem);

    dim3 ggrid(RR/128, 2048/128);   // (128, 16)
    dim3 lgrid(64, 2);

    reset_flags<<<1, 128>>>();
    gemm_xg<<<ggrid, 256>>>(0, sent, emb, w_ih, b_ih, b_hh);
    lstm_layer<<<lgrid, 256, lsmem>>>(0, w_hh, h0, c0);
    gemm_xg<<<ggrid, 256>>>(1, sent, emb, w_ih, b_ih, b_hh);
    lstm_layer<<<lgrid, 256, lsmem>>>(1, w_hh, h0, c0);
    feats_kernel<<<RR, 224>>>(w_out, b_out);

    int floatmode = (out_size == RR + BB) ? 1 : 0;
    viterbi_kernel<<<1, 448>>>(trans, d_out, floatmode);
}

// round 5
// speedup vs baseline: 1.1189x; 1.0135x over previous
#include <cuda_runtime.h>
#include <math.h>

// Problem constants
#define TT   256
#define BB   64
#define EE   512
#define HDD  256
#define NGG  1024         // 4*HD
#define KK   7
#define START_TAG 5
#define STOP_TAG  6
#define NEGV (-10000.0f)
#define RR   (TT*BB)      // 16384 rows

// ---------------- scratch (static device memory; no allocation) ----------------
__device__ float g_xg[2u * NGG * RR];       // [2048][16384] gate-major input gates
__device__ float g_xmid[(size_t)RR * 512];  // layer-0 output (concat hf|hb)
__device__ float g_xout[(size_t)RR * 512];  // layer-1 output
__device__ float g_h[4 * BB * HDD];         // [dir*2 + parity][64*256] h exchange
__device__ float g_feats[RR * KK];
__device__ unsigned char g_bp[TT * BB * 8];
__device__ unsigned int g_flags[2][64 * 8]; // per-CTA step flags, one per 32B sector

// =================================================================================
__global__ void reset_flags()
{
    int t = threadIdx.x;
    if (t < 128) g_flags[t >> 6][(t & 63) * 8] = 0u;
}

// =================================================================================
// fp32 GEMM (unchanged): xg[m][r] = bias[m] + sum_k A[m][k] * X[r][k]
// =================================================================================
__global__ void __launch_bounds__(256) gemm_xg(
    int layer,
    const int*   __restrict__ sent,
    const float* __restrict__ emb,
    const float* __restrict__ w_ih,
    const float* __restrict__ b_ih,
    const float* __restrict__ b_hh)
{
    __shared__ float As[16][132];
    __shared__ float Bs[16][132];

    const float* A    = w_ih + (size_t)layer * 2 * 1024 * 512;
    const float* bihL = b_ih + layer * 2048;
    const float* bhhL = b_hh + layer * 2048;
    const float* Bsrc;
    const int*   sidx;
    if (layer == 0) { Bsrc = emb;    sidx = sent; }
    else            { Bsrc = g_xmid; sidx = 0;    }

    int tid = threadIdx.x;
    int n0 = blockIdx.x * 128;
    int m0 = blockIdx.y * 128;
    int tx = tid & 15, ty = tid >> 4;

    int ar0 = tid >> 2;
    int ac0 = (tid & 3) * 4;

    int rn0 = n0 + ar0;
    int rn1 = n0 + ar0 + 64;
    const float* brow0 = Bsrc + (size_t)(sidx ? sidx[rn0] : rn0) * 512 + ac0;
    const float* brow1 = Bsrc + (size_t)(sidx ? sidx[rn1] : rn1) * 512 + ac0;
    const float* arow0 = A + (size_t)(m0 + ar0)      * 512 + ac0;
    const float* arow1 = A + (size_t)(m0 + ar0 + 64) * 512 + ac0;

    float acc[8][8];
#pragma unroll
    for (int i = 0; i < 8; i++)
#pragma unroll
        for (int j = 0; j < 8; j++) acc[i][j] = 0.f;

    for (int k0 = 0; k0 < 512; k0 += 16) {
        float4 a0 = *(const float4*)(arow0 + k0);
        float4 a1 = *(const float4*)(arow1 + k0);
        float4 b0 = *(const float4*)(brow0 + k0);
        float4 b1 = *(const float4*)(brow1 + k0);
        __syncthreads();
        As[ac0+0][ar0]    = a0.x; As[ac0+1][ar0]    = a0.y; As[ac0+2][ar0]    = a0.z; As[ac0+3][ar0]    = a0.w;
        As[ac0+0][ar0+64] = a1.x; As[ac0+1][ar0+64] = a1.y; As[ac0+2][ar0+64] = a1.z; As[ac0+3][ar0+64] = a1.w;
        Bs[ac0+0][ar0]    = b0.x; Bs[ac0+1][ar0]    = b0.y; Bs[ac0+2][ar0]    = b0.z; Bs[ac0+3][ar0]    = b0.w;
        Bs[ac0+0][ar0+64] = b1.x; Bs[ac0+1][ar0+64] = b1.y; Bs[ac0+2][ar0+64] = b1.z; Bs[ac0+3][ar0+64] = b1.w;
        __syncthreads();
#pragma unroll
        for (int kk = 0; kk < 16; kk++) {
            float a[8], b[8];
#pragma unroll
            for (int i = 0; i < 8; i++) a[i] = As[kk][ty*8 + i];
#pragma unroll
            for (int j = 0; j < 8; j++) b[j] = Bs[kk][tx*8 + j];
#pragma unroll
            for (int i = 0; i < 8; i++)
#pragma unroll
                for (int j = 0; j < 8; j++) acc[i][j] += a[i] * b[j];
        }
    }

#pragma unroll
    for (int i = 0; i < 8; i++) {
        int m = m0 + ty*8 + i;
        float bias = __ldg(&bihL[m]) + __ldg(&bhhL[m]);
        float* outp = g_xg + (size_t)m * RR + n0 + tx*8;
#pragma unroll
        for (int j = 0; j < 8; j++) outp[j] = acc[i][j] + bias;
    }
}

// =================================================================================
// Persistent bidirectional LSTM layer — 512 threads, K-split.
// Grid (64, 2). Each CTA owns 4 h-columns. Threads: b = tid&63, jl = (tid>>6)&3,
// hf = tid>>8. Each (b,jl) pair is handled by two threads, each doing K=128 of
// the 4 gate dot products; halves combined via a smem float4 reduction, gates
// computed by hf==0 threads. Per-CTA produce-flags for the cross-CTA exchange.
// =================================================================================
__global__ void __launch_bounds__(512) lstm_layer(
    int layer,
    const float* __restrict__ w_hh,
    const float* __restrict__ h0,
    const float* __restrict__ c0)
{
    extern __shared__ float sm[];
    float*  h_s = sm;                       // [64][260] padded
    float*  w_s = sm + 64 * 260;            // [16][256] : row = g*4 + jl
    float4* red = (float4*)(sm + 64 * 260 + 16 * 256);  // [256]

    const int d   = blockIdx.y;
    const int cta = blockIdx.x;             // 0..63
    const int j0  = cta * 4;
    const int tid = threadIdx.x;
    const int b   = tid & 63;
    const int jl  = (tid >> 6) & 3;
    const int hf  = tid >> 8;               // K half
    const int col = j0 + jl;

    const unsigned base = (unsigned)layer * (unsigned)TT;

    float* out_x = layer ? g_xout : g_xmid;
    const float* xg = g_xg + (size_t)d * NGG * RR;

    // stage this CTA's 16 W_hh rows into SMEM
    const float* wl = w_hh + (size_t)(layer*2 + d) * 1024 * 256;
    for (int idx = tid; idx < 16*256; idx += 512) {
        int rr = idx >> 8, k = idx & 255;
        int q = rr >> 2, jj = rr & 3;
        w_s[rr*256 + k] = wl[(size_t)(q*256 + j0 + jj)*256 + k];
    }

    float c = 0.f;
    if (hf == 0) c = c0[(2*layer + d) * (BB*HDD) + b*HDD + col];

    unsigned* myflag   = &g_flags[d][cta * 8];
    unsigned* pollflag = &g_flags[d][(tid & 63) * 8];

    for (int s = 0; s < TT; ++s) {
        int te  = d ? (TT - 1 - s) : s;
        int row = te * BB + b;

        // prefetch input gates (hf==0 threads; independent of the flag wait)
        float xgi = 0.f, xgf = 0.f, xgg = 0.f, xgo = 0.f;
        if (hf == 0) {
            xgi = __ldg(&xg[(size_t)(0*256 + col) * RR + row]);
            xgf = __ldg(&xg[(size_t)(1*256 + col) * RR + row]);
            xgg = __ldg(&xg[(size_t)(2*256 + col) * RR + row]);
            xgo = __ldg(&xg[(size_t)(3*256 + col) * RR + row]);
        }

        // wait for all 64 producer flags from step s-1
        if (s > 0 && tid < 64) {
            unsigned tgt = base + (unsigned)s;
            unsigned v;
            do {
                asm volatile("ld.global.cg.u32 %0, [%1];" : "=r"(v) : "l"(pollflag));
            } while (v < tgt);
        }
        __syncthreads();   // poll done; also protects h_s/red reuse

        const float* hsrc = (s == 0) ? (h0 + (2*layer + d) * (BB*HDD))
                                     : (g_h + (size_t)(d*2 + ((s+1)&1)) * (BB*HDD));
        for (int i = tid; i < 4096; i += 512) {
            float4 v = __ldcg(((const float4*)hsrc) + i);
            int fi = i * 4;
            *(float4*)(h_s + (fi >> 8) * 260 + (fi & 255)) = v;
        }
        __syncthreads();

        // half-dot over K=128
        float a0 = 0.f, a1 = 0.f, a2 = 0.f, a3 = 0.f;
        const int k0 = hf * 128;
        const float* hp = h_s + b * 260 + k0;
        const float* w0 = w_s + (0*4 + jl) * 256 + k0;
        const float* w1 = w_s + (1*4 + jl) * 256 + k0;
        const float* w2 = w_s + (2*4 + jl) * 256 + k0;
        const float* w3 = w_s + (3*4 + jl) * 256 + k0;
#pragma unroll 8
        for (int k = 0; k < 128; k += 4) {
            float4 hv = *(const float4*)(hp + k);
            float4 v0 = *(const float4*)(w0 + k);
            float4 v1 = *(const float4*)(w1 + k);
            float4 v2 = *(const float4*)(w2 + k);
            float4 v3 = *(const float4*)(w3 + k);
            a0 += hv.x*v0.x + hv.y*v0.y + hv.z*v0.z + hv.w*v0.w;
            a1 += hv.x*v1.x + hv.y*v1.y + hv.z*v1.z + hv.w*v1.w;
            a2 += hv.x*v2.x + hv.y*v2.y + hv.z*v2.z + hv.w*v2.w;
            a3 += hv.x*v3.x + hv.y*v3.y + hv.z*v3.z + hv.w*v3.w;
        }

        if (hf == 1) {
            red[jl*64 + b] = make_float4(a0, a1, a2, a3);
        }
        __syncthreads();

        if (hf == 0) {
            float4 p = red[jl*64 + b];
            a0 += p.x; a1 += p.y; a2 += p.z; a3 += p.w;

            float gi = 1.f / (1.f + expf(-(xgi + a0)));
            float gf = 1.f / (1.f + expf(-(xgf + a1)));
            float gg = tanhf(xgg + a2);
            float go = 1.f / (1.f + expf(-(xgo + a3)));
            c = gf * c + gi * gg;
            float h = go * tanhf(c);

            g_h[(size_t)(d*2 + (s & 1)) * (BB*HDD) + b*HDD + col] = h;
            out_x[(size_t)row * 512 + d*256 + col] = h;
        }

        // publish: make h visible, then raise this CTA's flag
        __threadfence();
        __syncthreads();
        if (tid == 0) {
            unsigned v = base + (unsigned)(s + 1);
            asm volatile("st.global.cg.u32 [%0], %1;" :: "l"(myflag), "r"(v));
        }
    }
}

// =================================================================================
__global__ void feats_kernel(const float* __restrict__ wout,
                             const float* __restrict__ bout)
{
    int r = blockIdx.x;
    int w = threadIdx.x >> 5;
    int lane = threadIdx.x & 31;
    const float* xr = g_xout + (size_t)r * 512;
    const float* wr = wout + w * 512;
    float acc = 0.f;
#pragma unroll
    for (int i = 0; i < 16; i++) {
        int e = lane + i * 32;
        acc += xr[e] * wr[e];
    }
#pragma unroll
    for (int o = 16; o; o >>= 1) acc += __shfl_down_sync(0xffffffffu, acc, o);
    if (lane == 0) g_feats[r * KK + w] = acc + bout[w];
}

// =================================================================================
__global__ void viterbi_kernel(const float* __restrict__ trans,
                               void* out, int floatmode)
{
    __shared__ float vbuf[2][64][8];
    __shared__ float tr[7][7];

    int tid = threadIdx.x;
    if (tid < 49) tr[tid / 7][tid % 7] = trans[tid];
    int b  = tid & 63;
    int nx = tid >> 6;
    vbuf[0][b][nx] = (nx == START_TAG) ? 0.f : NEGV;
    __syncthreads();

    int p = 0;
    for (int t = 0; t < TT; ++t) {
        float best = vbuf[p][b][0] + tr[nx][0];
        int   bp   = 0;
#pragma unroll
        for (int pv = 1; pv < 7; ++pv) {
            float cnd = vbuf[p][b][pv] + tr[nx][pv];
            if (cnd > best) { best = cnd; bp = pv; }
        }
        vbuf[p ^ 1][b][nx] = best + g_feats[(t*BB + b) * KK + nx];
        g_bp[(t*BB + b) * 8 + nx] = (unsigned char)bp;
        __syncthreads();
        p ^= 1;
    }

    if (tid < 64) {
        float bestt = vbuf[p][tid][0] + tr[STOP_TAG][0];
        int   lastt = 0;
#pragma unroll
        for (int k2 = 1; k2 < 7; ++k2) {
            float cnd = vbuf[p][tid][k2] + tr[STOP_TAG][k2];
            if (cnd > bestt) { bestt = cnd; lastt = k2; }
        }
        int tag = lastt;
        if (floatmode) {
            float* fo = (float*)out;
            fo[RR + tid] = bestt;
            for (int t = TT - 1; t >= 0; --t) {
                fo[tid * TT + t] = (float)tag;
                tag = g_bp[(t*BB + tid) * 8 + tag];
            }
        } else {
            int* io = (int*)out;
            for (int t = TT - 1; t >= 0; --t) {
                io[tid * TT + t] = tag;
                tag = g_bp[(t*BB + tid) * 8 + tag];
            }
        }
    }
}

// =================================================================================
extern "C" void kernel_launch(void* const* d_in, const int* in_sizes, int n_in,
                              void* d_out, int out_size)
{
    const int*   sent  = (const int*)  d_in[0];
    const float* emb   = (const float*)d_in[1];
    const float* w_ih  = (const float*)d_in[2];
    const float* w_hh  = (const float*)d_in[3];
    const float* b_ih  = (const float*)d_in[4];
    const float* b_hh  = (const float*)d_in[5];
    const float* w_out = (const float*)d_in[6];
    const float* b_out = (const float*)d_in[7];
    const float* trans = (const float*)d_in[8];
    const float* h0    = (const float*)d_in[9];
    const float* c0    = (const float*)d_in[10];

    size_t lsmem = (size_t)(64*260 + 16*256 + 256*4) * sizeof(float);   // ~87 KB
    cudaFuncSetAttribute(lstm_layer, cudaFuncAttributeMaxDynamicSharedMemorySize, (int)lsmem);

    dim3 ggrid(RR/128, 2048/128);   // (128, 16)
    dim3 lgrid(64, 2);

    reset_flags<<<1, 128>>>();
    gemm_xg<<<ggrid, 256>>>(0, sent, emb, w_ih, b_ih, b_hh);
    lstm_layer<<<lgrid, 512, lsmem>>>(0, w_hh, h0, c0);
    gemm_xg<<<ggrid, 256>>>(1, sent, emb, w_ih, b_ih, b_hh);
    lstm_layer<<<lgrid, 512, lsmem>>>(1, w_hh, h0, c0);
    feats_kernel<<<RR, 224>>>(w_out, b_out);

    int floatmode = (out_size == RR + BB) ? 1 : 0;
    viterbi_kernel<<<1, 448>>>(trans, d_out, floatmode);
}

// round 7
// speedup vs baseline: 1.2984x; 1.1604x over previous
#include <cuda_runtime.h>
#include <math.h>

// Problem constants
#define TT   256
#define BB   64
#define EE   512
#define HDD  256
#define NGG  1024         // 4*HD
#define KK   7
#define START_TAG 5
#define STOP_TAG  6
#define NEGV (-10000.0f)
#define RR   (TT*BB)      // 16384 rows
#define HTBUF (HDD*BB)    // 16384 floats per h buffer

// ---------------- scratch (static device memory; no allocation) ----------------
__device__ float g_xg[2u * NGG * RR];       // [2048][16384] gate-major input gates
__device__ float g_xT[(size_t)512 * RR];    // layer output, TRANSPOSED: [e][t*64+b]
__device__ float g_hT[4 * HTBUF];           // [dir*2+parity][col*64+b] h exchange
__device__ float g_feats[RR * KK];
__device__ unsigned char g_bp[TT * BB * 8];
__device__ unsigned int g_flags[2][64 * 8]; // per-CTA step flags, one per 32B sector

// =================================================================================
__global__ void reset_flags()
{
    int t = threadIdx.x;
    if (t < 128) g_flags[t >> 6][(t & 63) * 8] = 0u;
}

// =================================================================================
// transpose h0 slice for this layer into the parity-1 h buffers (read at s==0)
// grid (64, 2), 256 threads
// =================================================================================
__global__ void prep_layer(int layer, const float* __restrict__ h0)
{
    int d   = blockIdx.y;
    int col = blockIdx.x * 4 + (threadIdx.x >> 6);
    int b   = threadIdx.x & 63;
    g_hT[(d*2 + 1) * HTBUF + col * 64 + b] =
        h0[(2*layer + d) * (BB*HDD) + b * HDD + col];
}

// =================================================================================
// fp32 GEMM: xg[m][r] = bias[m] + sum_k A[m][k] * X[r][k], gate-major output.
// layer 0: X rows gathered from emb via sentence ids.
// layer 1: X read from g_xT (transposed layer-0 output) -> coalesced k-major load.
// =================================================================================
__global__ void __launch_bounds__(256) gemm_xg(
    int layer,
    const int*   __restrict__ sent,
    const float* __restrict__ emb,
    const float* __restrict__ w_ih,
    const float* __restrict__ b_ih,
    const float* __restrict__ b_hh)
{
    __shared__ float As[16][132];
    __shared__ float Bs[16][132];

    const float* A    = w_ih + (size_t)layer * 2 * 1024 * 512;
    const float* bihL = b_ih + layer * 2048;
    const float* bhhL = b_hh + layer * 2048;

    int tid = threadIdx.x;
    int n0 = blockIdx.x * 128;
    int m0 = blockIdx.y * 128;
    int tx = tid & 15, ty = tid >> 4;

    int ar0 = tid >> 2;
    int ac0 = (tid & 3) * 4;

    // layer-0 gathered row pointers
    const float* brow0 = 0;
    const float* brow1 = 0;
    if (layer == 0) {
        brow0 = emb + (size_t)sent[n0 + ar0]      * 512 + ac0;
        brow1 = emb + (size_t)sent[n0 + ar0 + 64] * 512 + ac0;
    }
    // layer-1 transposed-load coords
    int kk1 = tid >> 4;          // 0..15
    int r4  = tid & 15;          // 0..15

    const float* arow0 = A + (size_t)(m0 + ar0)      * 512 + ac0;
    const float* arow1 = A + (size_t)(m0 + ar0 + 64) * 512 + ac0;

    float acc[8][8];
#pragma unroll
    for (int i = 0; i < 8; i++)
#pragma unroll
        for (int j = 0; j < 8; j++) acc[i][j] = 0.f;

    for (int k0 = 0; k0 < 512; k0 += 16) {
        float4 a0 = *(const float4*)(arow0 + k0);
        float4 a1 = *(const float4*)(arow1 + k0);
        float4 b0, b1;
        if (layer == 0) {
            b0 = *(const float4*)(brow0 + k0);
            b1 = *(const float4*)(brow1 + k0);
        } else {
            const float* src = g_xT + (size_t)(k0 + kk1) * RR + n0;
            b0 = *(const float4*)(src + r4 * 4);
            b1 = *(const float4*)(src + r4 * 4 + 64);
        }
        __syncthreads();
        As[ac0+0][ar0]    = a0.x; As[ac0+1][ar0]    = a0.y; As[ac0+2][ar0]    = a0.z; As[ac0+3][ar0]    = a0.w;
        As[ac0+0][ar0+64] = a1.x; As[ac0+1][ar0+64] = a1.y; As[ac0+2][ar0+64] = a1.z; As[ac0+3][ar0+64] = a1.w;
        if (layer == 0) {
            Bs[ac0+0][ar0]    = b0.x; Bs[ac0+1][ar0]    = b0.y; Bs[ac0+2][ar0]    = b0.z; Bs[ac0+3][ar0]    = b0.w;
            Bs[ac0+0][ar0+64] = b1.x; Bs[ac0+1][ar0+64] = b1.y; Bs[ac0+2][ar0+64] = b1.z; Bs[ac0+3][ar0+64] = b1.w;
        } else {
            *(float4*)&Bs[kk1][r4*4]      = b0;
            *(float4*)&Bs[kk1][r4*4 + 64] = b1;
        }
        __syncthreads();
#pragma unroll
        for (int kk = 0; kk < 16; kk++) {
            float a[8], b[8];
#pragma unroll
            for (int i = 0; i < 8; i++) a[i] = As[kk][ty*8 + i];
#pragma unroll
            for (int j = 0; j < 8; j++) b[j] = Bs[kk][tx*8 + j];
#pragma unroll
            for (int i = 0; i < 8; i++)
#pragma unroll
                for (int j = 0; j < 8; j++) acc[i][j] += a[i] * b[j];
        }
    }

#pragma unroll
    for (int i = 0; i < 8; i++) {
        int m = m0 + ty*8 + i;
        float bias = __ldg(&bihL[m]) + __ldg(&bhhL[m]);
        float* outp = g_xg + (size_t)m * RR + n0 + tx*8;
#pragma unroll
        for (int j = 0; j < 8; j++) outp[j] = acc[i][j] + bias;
    }
}

// =================================================================================
// Persistent bidirectional LSTM layer — register outer-product formulation.
// Grid (64, 2): 64 CTAs per direction, each owns 4 h-cols = 16 W-rows.
// 512 threads = 32 lanes (b, b+32) x 16 k-splits (16 k each).
// Per k: 2 scalar h loads from transposed global h (L2, read-once), 4 broadcast
// LDS.128 of W, 32 FMA into 16x2 register accumulators. Partials reduced via a
// conflict-free smem buffer; 256 gate threads do the nonlinearity + publish.
// Cross-CTA exchange: per-CTA flags with release/acquire semantics.
// =================================================================================
__global__ void __launch_bounds__(512) lstm_layer(
    int layer,
    const float* __restrict__ w_hh,
    const float* __restrict__ c0)
{
    extern __shared__ float sm[];
    float* w_s = sm;                 // [k=256][o=16]  16 KB
    float* red = sm + 256 * 16;      // [o=16][sp=16][b=64]  64 KB

    const int d    = blockIdx.y;
    const int cta  = blockIdx.x;     // 0..63
    const int j0   = cta * 4;
    const int tid  = threadIdx.x;
    const int lane = tid & 31;
    const int sp   = tid >> 5;       // 0..15

    const unsigned base = (unsigned)layer * (unsigned)TT;

    // stage this CTA's 16 W rows transposed: w_s[k*16 + o], o = gate*4 + jj
    const float* wl = w_hh + (size_t)(layer*2 + d) * 1024 * 256;
    for (int i = tid; i < 4096; i += 512) {
        int o = i >> 8, k = i & 255;
        int g = o >> 2, jj = o & 3;
        w_s[k*16 + o] = wl[(size_t)(g*256 + j0 + jj)*256 + k];
    }

    // gate-thread state
    const int gb  = tid & 63;
    const int jl  = (tid >> 6) & 3;
    const int col = j0 + jl;
    float c = 0.f;
    if (tid < 256) c = c0[(2*layer + d)*(BB*HDD) + gb*HDD + col];

    const float* xg = g_xg + (size_t)d * NGG * RR;
    unsigned* myflag   = &g_flags[d][cta * 8];
    unsigned* pollflag = &g_flags[d][(tid & 63) * 8];
    float* hT_d = g_hT + (d*2) * HTBUF;

    __syncthreads();   // w_s ready

    for (int s = 0; s < TT; ++s) {
        int te = d ? (TT - 1 - s) : s;

        // xg prefetch (gate threads; independent of flag wait)
        float xgi = 0.f, xgf = 0.f, xgg = 0.f, xgo = 0.f;
        if (tid < 256) {
            int row = te * 64 + gb;
            xgi = __ldg(&xg[(size_t)(0*256 + col) * RR + row]);
            xgf = __ldg(&xg[(size_t)(1*256 + col) * RR + row]);
            xgg = __ldg(&xg[(size_t)(2*256 + col) * RR + row]);
            xgo = __ldg(&xg[(size_t)(3*256 + col) * RR + row]);
        }

        // wait for all 64 producer flags from step s-1
        if (s > 0 && tid < 64) {
            unsigned tgt = base + (unsigned)s;
            unsigned v;
            do {
                asm volatile("ld.acquire.gpu.global.u32 %0, [%1];" : "=r"(v) : "l"(pollflag));
            } while (v < tgt);
        }
        __syncthreads();   // flags seen by all; also guards red reuse

        // mainloop: 16 k, 16 outs, 2 b's
        const float* hp = hT_d + ((s+1)&1) * HTBUF;
        float acc0[16], acc1[16];
#pragma unroll
        for (int o = 0; o < 16; o++) { acc0[o] = 0.f; acc1[o] = 0.f; }
        const int k0 = sp * 16;
#pragma unroll
        for (int kk = 0; kk < 16; ++kk) {
            int k = k0 + kk;
            float h0v = __ldcg(&hp[k*64 + lane]);
            float h1v = __ldcg(&hp[k*64 + lane + 32]);
            const float4* wp = (const float4*)(w_s + k*16);
            float4 wA = wp[0], wB = wp[1], wC = wp[2], wD = wp[3];
            acc0[ 0] += wA.x*h0v; acc1[ 0] += wA.x*h1v;
            acc0[ 1] += wA.y*h0v; acc1[ 1] += wA.y*h1v;
            acc0[ 2] += wA.z*h0v; acc1[ 2] += wA.z*h1v;
            acc0[ 3] += wA.w*h0v; acc1[ 3] += wA.w*h1v;
            acc0[ 4] += wB.x*h0v; acc1[ 4] += wB.x*h1v;
            acc0[ 5] += wB.y*h0v; acc1[ 5] += wB.y*h1v;
            acc0[ 6] += wB.z*h0v; acc1[ 6] += wB.z*h1v;
            acc0[ 7] += wB.w*h0v; acc1[ 7] += wB.w*h1v;
            acc0[ 8] += wC.x*h0v; acc1[ 8] += wC.x*h1v;
            acc0[ 9] += wC.y*h0v; acc1[ 9] += wC.y*h1v;
            acc0[10] += wC.z*h0v; acc1[10] += wC.z*h1v;
            acc0[11] += wC.w*h0v; acc1[11] += wC.w*h1v;
            acc0[12] += wD.x*h0v; acc1[12] += wD.x*h1v;
            acc0[13] += wD.y*h0v; acc1[13] += wD.y*h1v;
            acc0[14] += wD.z*h0v; acc1[14] += wD.z*h1v;
            acc0[15] += wD.w*h0v; acc1[15] += wD.w*h1v;
        }
        // write partials: red[o][sp][b]  (lanes consecutive b -> conflict-free)
#pragma unroll
        for (int o = 0; o < 16; ++o) {
            red[o*1024 + sp*64 + lane]      = acc0[o];
            red[o*1024 + sp*64 + lane + 32] = acc1[o];
        }
        __syncthreads();

        if (tid < 256) {
            float a[4];
#pragma unroll
            for (int g = 0; g < 4; ++g) {
                int o = g*4 + jl;
                float ssum = 0.f;
#pragma unroll
                for (int q = 0; q < 16; ++q) ssum += red[o*1024 + q*64 + gb];
                a[g] = ssum;
            }
            float gi = 1.f / (1.f + expf(-(xgi + a[0])));
            float gf = 1.f / (1.f + expf(-(xgf + a[1])));
            float gg = tanhf(xgg + a[2]);
            float go = 1.f / (1.f + expf(-(xgo + a[3])));
            c = gf * c + gi * gg;
            float h = go * tanhf(c);

            // publish h (transposed, coalesced, L2)
            asm volatile("st.global.cg.f32 [%0], %1;"
                         :: "l"(&hT_d[(s&1)*HTBUF + col*64 + gb]), "f"(h) : "memory");
            // layer output (transposed, coalesced)
            g_xT[(size_t)(d*256 + col) * RR + te*64 + gb] = h;
        }
        __syncthreads();
        if (tid == 0) {
            unsigned v = base + (unsigned)(s + 1);
            asm volatile("st.release.gpu.global.u32 [%0], %1;" :: "l"(myflag), "r"(v) : "memory");
        }
    }
}

// =================================================================================
// feats from transposed input: feats[r][k] = b_out[k] + sum_e g_xT[e][r]*w_out[k][e]
// grid 128 blocks x 128 threads; block owns 128 consecutive r.
// =================================================================================
__global__ void __launch_bounds__(128) feats_T(
    const float* __restrict__ wout,
    const float* __restrict__ bout)
{
    __shared__ float ws[512 * 8];          // [e][k] k<7, slot 7 = pad
    int tid = threadIdx.x;
    int r = blockIdx.x * 128 + tid;

    for (int i = tid; i < 512 * 8; i += 128) {
        int e = i >> 3, k = i & 7;
        ws[i] = (k < 7) ? __ldg(&wout[k * 512 + e]) : 0.f;
    }
    __syncthreads();

    float acc[8];
#pragma unroll
    for (int k = 0; k < 8; k++) acc[k] = (k < 7) ? __ldg(&bout[k]) : 0.f;

#pragma unroll 4
    for (int e = 0; e < 512; ++e) {
        float x = __ldg(&g_xT[(size_t)e * RR + r]);
        float4 wa = *(const float4*)(ws + e*8);
        float4 wb = *(const float4*)(ws + e*8 + 4);
        acc[0] += x * wa.x; acc[1] += x * wa.y; acc[2] += x * wa.z; acc[3] += x * wa.w;
        acc[4] += x * wb.x; acc[5] += x * wb.y; acc[6] += x * wb.z;
    }
#pragma unroll
    for (int k = 0; k < 7; ++k) g_feats[r * KK + k] = acc[k];
}

// =================================================================================
// Viterbi: 448 threads = 64 batch x 7 next-tags
// =================================================================================
__global__ void viterbi_kernel(const float* __restrict__ trans,
                               void* out, int floatmode)
{
    __shared__ float vbuf[2][64][8];
    __shared__ float tr[7][7];

    int tid = threadIdx.x;
    if (tid < 49) tr[tid / 7][tid % 7] = trans[tid];
    int b  = tid & 63;
    int nx = tid >> 6;
    vbuf[0][b][nx] = (nx == START_TAG) ? 0.f : NEGV;
    __syncthreads();

    int p = 0;
    for (int t = 0; t < TT; ++t) {
        float best = vbuf[p][b][0] + tr[nx][0];
        int   bp   = 0;
#pragma unroll
        for (int pv = 1; pv < 7; ++pv) {
            float cnd = vbuf[p][b][pv] + tr[nx][pv];
            if (cnd > best) { best = cnd; bp = pv; }
        }
        vbuf[p ^ 1][b][nx] = best + g_feats[(t*BB + b) * KK + nx];
        g_bp[(t*BB + b) * 8 + nx] = (unsigned char)bp;
        __syncthreads();
        p ^= 1;
    }

    if (tid < 64) {
        float bestt = vbuf[p][tid][0] + tr[STOP_TAG][0];
        int   lastt = 0;
#pragma unroll
        for (int k2 = 1; k2 < 7; ++k2) {
            float cnd = vbuf[p][tid][k2] + tr[STOP_TAG][k2];
            if (cnd > bestt) { bestt = cnd; lastt = k2; }
        }
        int tag = lastt;
        if (floatmode) {
            float* fo = (float*)out;
            fo[RR + tid] = bestt;
            for (int t = TT - 1; t >= 0; --t) {
                fo[tid * TT + t] = (float)tag;
                tag = g_bp[(t*BB + tid) * 8 + tag];
            }
        } else {
            int* io = (int*)out;
            for (int t = TT - 1; t >= 0; --t) {
                io[tid * TT + t] = tag;
                tag = g_bp[(t*BB + tid) * 8 + tag];
            }
        }
    }
}

// =================================================================================
extern "C" void kernel_launch(void* const* d_in, const int* in_sizes, int n_in,
                              void* d_out, int out_size)
{
    const int*   sent  = (const int*)  d_in[0];
    const float* emb   = (const float*)d_in[1];
    const float* w_ih  = (const float*)d_in[2];
    const float* w_hh  = (const float*)d_in[3];
    const float* b_ih  = (const float*)d_in[4];
    const float* b_hh  = (const float*)d_in[5];
    const float* w_out = (const float*)d_in[6];
    const float* b_out = (const float*)d_in[7];
    const float* trans = (const float*)d_in[8];
    const float* h0    = (const float*)d_in[9];
    const float* c0    = (const float*)d_in[10];

    size_t lsmem = (size_t)(256*16 + 16*16*64) * sizeof(float);   // 80 KB
    cudaFuncSetAttribute(lstm_layer, cudaFuncAttributeMaxDynamicSharedMemorySize, (int)lsmem);

    dim3 ggrid(RR/128, 2048/128);   // (128, 16)
    dim3 lgrid(64, 2);

    reset_flags<<<1, 128>>>();

    prep_layer<<<lgrid, 256>>>(0, h0);
    gemm_xg<<<ggrid, 256>>>(0, sent, emb, w_ih, b_ih, b_hh);
    lstm_layer<<<lgrid, 512, lsmem>>>(0, w_hh, c0);

    prep_layer<<<lgrid, 256>>>(1, h0);
    gemm_xg<<<ggrid, 256>>>(1, sent, emb, w_ih, b_ih, b_hh);
    lstm_layer<<<lgrid, 512, lsmem>>>(1, w_hh, c0);

    feats_T<<<128, 128>>>(w_out, b_out);

    int floatmode = (out_size == RR + BB) ? 1 : 0;
    viterbi_kernel<<<1, 448>>>(trans, d_out, floatmode);
}

// round 8
// speedup vs baseline: 1.4400x; 1.1090x over previous
#include <cuda_runtime.h>
#include <math.h>
#include <stdint.h>

// Problem constants
#define TT   256
#define BB   64
#define EE   512
#define HDD  256
#define NGG  1024         // 4*HD
#define KK   7
#define START_TAG 5
#define STOP_TAG  6
#define NEGV (-10000.0f)
#define RR   (TT*BB)      // 16384 rows
#define HTBUF (HDD*BB)    // 16384 floats per h buffer

// ---------------- scratch (static device memory; no allocation) ----------------
__device__ float g_xg[2u * NGG * RR];       // [2048][16384] gate-major input gates
__device__ float g_xT[(size_t)512 * RR];    // layer output, TRANSPOSED: [e][t*64+b]
__device__ float g_bT[(size_t)512 * RR];    // layer-0 GEMM B, transposed: [e][r]
__device__ float g_wT[2 * 512 * 2048];      // w_ih transposed per layer: [k][m]
__device__ float g_hT[4 * HTBUF];           // [dir*2+parity][col*64+b] h exchange
__device__ float g_feats[RR * KK];
__device__ unsigned char g_bp[TT * BB * 8];
__device__ unsigned int g_flags[2][64 * 8]; // per-CTA step flags, one per 32B sector

// ---------------------------------------------------------------------------------
__device__ __forceinline__ void cpasync16(uint32_t s, const void* g) {
    asm volatile("cp.async.cg.shared.global [%0], [%1], 16;\n" :: "r"(s), "l"(g));
}
__device__ __forceinline__ void cpcommit() { asm volatile("cp.async.commit_group;\n"); }
template<int N> __device__ __forceinline__ void cpwait() {
    asm volatile("cp.async.wait_group %0;\n" :: "n"(N));
}

// =================================================================================
__global__ void reset_flags()
{
    int t = threadIdx.x;
    if (t < 128) g_flags[t >> 6][(t & 63) * 8] = 0u;
}

// =================================================================================
// transpose w_ih[layer][m][k] -> g_wT[layer][k][m]; grid (64, 16, 2), 256 thr
// =================================================================================
__global__ void __launch_bounds__(256) prep_wT(const float* __restrict__ w_ih)
{
    __shared__ float sm[32][33];
    int L  = blockIdx.z;
    int m0 = blockIdx.x * 32, k0 = blockIdx.y * 32;
    int t  = threadIdx.x;

    int mr = t >> 3, kc4 = (t & 7) * 4;
    float4 v = *(const float4*)(w_ih + (size_t)L*2048*512 + (size_t)(m0+mr)*512 + k0 + kc4);
    sm[mr][kc4+0] = v.x; sm[mr][kc4+1] = v.y; sm[mr][kc4+2] = v.z; sm[mr][kc4+3] = v.w;
    __syncthreads();

    int kr = t >> 3, mc4 = (t & 7) * 4;
    float4 o;
    o.x = sm[mc4+0][kr]; o.y = sm[mc4+1][kr]; o.z = sm[mc4+2][kr]; o.w = sm[mc4+3][kr];
    *(float4*)(g_wT + (size_t)L*512*2048 + (size_t)(k0+kr)*2048 + m0 + mc4) = o;
}

// =================================================================================
// gather embeddings transposed: g_bT[e][r] = emb[sent[r]][e]; 1024 blocks x 256
// =================================================================================
__global__ void __launch_bounds__(256) gather_T(const int* __restrict__ sent,
                                                const float* __restrict__ emb)
{
    __shared__ float sm[16 * 513];
    int t  = threadIdx.x;
    int r0 = blockIdx.x * 16;

#pragma unroll
    for (int i = 0; i < 8; i++) {
        int idx = i * 256 + t;
        int r = idx >> 7, c4 = (idx & 127) * 4;
        float4 v = __ldg((const float4*)(emb + (size_t)sent[r0+r] * 512 + c4));
        sm[r*513 + c4+0] = v.x; sm[r*513 + c4+1] = v.y;
        sm[r*513 + c4+2] = v.z; sm[r*513 + c4+3] = v.w;
    }
    __syncthreads();

    int r = t & 15, e0 = t >> 4;
#pragma unroll
    for (int j = 0; j < 32; j++) {
        int e = j * 16 + e0;
        g_bT[(size_t)e * RR + r0 + r] = sm[r*513 + e];
    }
}

// =================================================================================
// transpose h0 slice for this layer into the parity-1 h buffers (read at s==0)
// =================================================================================
__global__ void prep_layer(int layer, const float* __restrict__ h0)
{
    int d   = blockIdx.y;
    int col = blockIdx.x * 4 + (threadIdx.x >> 6);
    int b   = threadIdx.x & 63;
    g_hT[(d*2 + 1) * HTBUF + col * 64 + b] =
        h0[(2*layer + d) * (BB*HDD) + b * HDD + col];
}

// =================================================================================
// Double-buffered cp.async GEMM: xg[m][r] = bias[m] + sum_k wT[k][m] * BT[k][r].
// Both operands k-major in global (g_wT; g_bT for layer 0, g_xT for layer 1).
// 128x128 tile, k-chunk 16, 2 stages, 256 threads, 8x8 microtile.
// =================================================================================
__global__ void __launch_bounds__(256) gemm_db(
    int layer,
    const float* __restrict__ b_ih,
    const float* __restrict__ b_hh)
{
    __shared__ float As[2][16][128];
    __shared__ float Bs[2][16][128];

    const float* AT   = g_wT + (size_t)layer * 512 * 2048;
    const float* BT   = layer ? g_xT : g_bT;
    const float* bihL = b_ih + layer * 2048;
    const float* bhhL = b_hh + layer * 2048;

    int tid = threadIdx.x;
    int n0 = blockIdx.x * 128;
    int m0 = blockIdx.y * 128;
    int tx = tid & 15, ty = tid >> 4;

    float acc[8][8];
#pragma unroll
    for (int i = 0; i < 8; i++)
#pragma unroll
        for (int j = 0; j < 8; j++) acc[i][j] = 0.f;

    auto stage = [&](int k0, int buf) {
#pragma unroll
        for (int i = 0; i < 2; i++) {
            int id = i * 256 + tid;
            int rw = id >> 5, sg = id & 31;
            cpasync16((uint32_t)__cvta_generic_to_shared(&As[buf][rw][sg*4]),
                      AT + (size_t)(k0 + rw) * 2048 + m0 + sg*4);
        }
#pragma unroll
        for (int i = 0; i < 2; i++) {
            int id = i * 256 + tid;
            int rw = id >> 5, sg = id & 31;
            cpasync16((uint32_t)__cvta_generic_to_shared(&Bs[buf][rw][sg*4]),
                      BT + (size_t)(k0 + rw) * RR + n0 + sg*4);
        }
    };

    stage(0, 0);  cpcommit();
    stage(16, 1); cpcommit();

    for (int c = 0; c < 32; c++) {
        if (c == 31) cpwait<0>(); else cpwait<1>();
        __syncthreads();
        int buf = c & 1;
#pragma unroll
        for (int kk = 0; kk < 16; kk++) {
            float a[8], b[8];
            *(float4*)&a[0] = *(const float4*)&As[buf][kk][ty*8];
            *(float4*)&a[4] = *(const float4*)&As[buf][kk][ty*8 + 4];
            *(float4*)&b[0] = *(const float4*)&Bs[buf][kk][tx*8];
            *(float4*)&b[4] = *(const float4*)&Bs[buf][kk][tx*8 + 4];
#pragma unroll
            for (int i = 0; i < 8; i++)
#pragma unroll
                for (int j = 0; j < 8; j++) acc[i][j] += a[i] * b[j];
        }
        __syncthreads();
        if (c + 2 < 32) { stage((c + 2) * 16, buf); cpcommit(); }
    }

#pragma unroll
    for (int i = 0; i < 8; i++) {
        int m = m0 + ty*8 + i;
        float bias = __ldg(&bihL[m]) + __ldg(&bhhL[m]);
        float* outp = g_xg + (size_t)m * RR + n0 + tx*8;
#pragma unroll
        for (int j = 0; j < 8; j++) outp[j] = acc[i][j] + bias;
    }
}

// =================================================================================
// Persistent bidirectional LSTM layer — register outer-product formulation.
// Grid (64, 2). 512 threads = 32 lanes x 16 k-splits. h loads hoisted into
// registers (MLP=32) before the FMA loop. Per-CTA release/acquire flags.
// =================================================================================
__global__ void __launch_bounds__(512) lstm_layer(
    int layer,
    const float* __restrict__ w_hh,
    const float* __restrict__ c0)
{
    extern __shared__ float sm[];
    float* w_s = sm;                 // [k=256][o=16]  16 KB
    float* red = sm + 256 * 16;      // [o=16][sp=16][b=64]  64 KB

    const int d    = blockIdx.y;
    const int cta  = blockIdx.x;     // 0..63
    const int j0   = cta * 4;
    const int tid  = threadIdx.x;
    const int lane = tid & 31;
    const int sp   = tid >> 5;       // 0..15

    const unsigned base = (unsigned)layer * (unsigned)TT;

    // stage this CTA's 16 W rows transposed: w_s[k*16 + o], o = gate*4 + jj
    const float* wl = w_hh + (size_t)(layer*2 + d) * 1024 * 256;
    for (int i = tid; i < 4096; i += 512) {
        int o = i >> 8, k = i & 255;
        int g = o >> 2, jj = o & 3;
        w_s[k*16 + o] = wl[(size_t)(g*256 + j0 + jj)*256 + k];
    }

    // gate-thread state
    const int gb  = tid & 63;
    const int jl  = (tid >> 6) & 3;
    const int col = j0 + jl;
    float c = 0.f;
    if (tid < 256) c = c0[(2*layer + d)*(BB*HDD) + gb*HDD + col];

    const float* xg = g_xg + (size_t)d * NGG * RR;
    unsigned* myflag   = &g_flags[d][cta * 8];
    unsigned* pollflag = &g_flags[d][(tid & 63) * 8];
    float* hT_d = g_hT + (d*2) * HTBUF;

    __syncthreads();   // w_s ready

    for (int s = 0; s < TT; ++s) {
        int te = d ? (TT - 1 - s) : s;

        // xg prefetch (gate threads; independent of flag wait)
        float xgi = 0.f, xgf = 0.f, xgg = 0.f, xgo = 0.f;
        if (tid < 256) {
            int row = te * 64 + gb;
            xgi = __ldg(&xg[(size_t)(0*256 + col) * RR + row]);
            xgf = __ldg(&xg[(size_t)(1*256 + col) * RR + row]);
            xgg = __ldg(&xg[(size_t)(2*256 + col) * RR + row]);
            xgo = __ldg(&xg[(size_t)(3*256 + col) * RR + row]);
        }

        // wait for all 64 producer flags from step s-1
        if (s > 0 && tid < 64) {
            unsigned tgt = base + (unsigned)s;
            unsigned v;
            do {
                asm volatile("ld.acquire.gpu.global.u32 %0, [%1];" : "=r"(v) : "l"(pollflag));
            } while (v < tgt);
        }
        __syncthreads();   // flags seen by all; also guards red reuse

        // hoisted h loads: 32 outstanding L2 loads, one exposed latency
        const float* hp = hT_d + ((s+1)&1) * HTBUF;
        const int k0 = sp * 16;
        float hv0[16], hv1[16];
#pragma unroll
        for (int kk = 0; kk < 16; ++kk) {
            hv0[kk] = __ldcg(&hp[(k0+kk)*64 + lane]);
            hv1[kk] = __ldcg(&hp[(k0+kk)*64 + lane + 32]);
        }

        float acc0[16], acc1[16];
#pragma unroll
        for (int o = 0; o < 16; o++) { acc0[o] = 0.f; acc1[o] = 0.f; }
#pragma unroll
        for (int kk = 0; kk < 16; ++kk) {
            int k = k0 + kk;
            float h0v = hv0[kk], h1v = hv1[kk];
            const float4* wp = (const float4*)(w_s + k*16);
            float4 wA = wp[0], wB = wp[1], wC = wp[2], wD = wp[3];
            acc0[ 0] += wA.x*h0v; acc1[ 0] += wA.x*h1v;
            acc0[ 1] += wA.y*h0v; acc1[ 1] += wA.y*h1v;
            acc0[ 2] += wA.z*h0v; acc1[ 2] += wA.z*h1v;
            acc0[ 3] += wA.w*h0v; acc1[ 3] += wA.w*h1v;
            acc0[ 4] += wB.x*h0v; acc1[ 4] += wB.x*h1v;
            acc0[ 5] += wB.y*h0v; acc1[ 5] += wB.y*h1v;
            acc0[ 6] += wB.z*h0v; acc1[ 6] += wB.z*h1v;
            acc0[ 7] += wB.w*h0v; acc1[ 7] += wB.w*h1v;
            acc0[ 8] += wC.x*h0v; acc1[ 8] += wC.x*h1v;
            acc0[ 9] += wC.y*h0v; acc1[ 9] += wC.y*h1v;
            acc0[10] += wC.z*h0v; acc1[10] += wC.z*h1v;
            acc0[11] += wC.w*h0v; acc1[11] += wC.w*h1v;
            acc0[12] += wD.x*h0v; acc1[12] += wD.x*h1v;
            acc0[13] += wD.y*h0v; acc1[13] += wD.y*h1v;
            acc0[14] += wD.z*h0v; acc1[14] += wD.z*h1v;
            acc0[15] += wD.w*h0v; acc1[15] += wD.w*h1v;
        }
        // write partials: red[o][sp][b]  (lanes consecutive b -> conflict-free)
#pragma unroll
        for (int o = 0; o < 16; ++o) {
            red[o*1024 + sp*64 + lane]      = acc0[o];
            red[o*1024 + sp*64 + lane + 32] = acc1[o];
        }
        __syncthreads();

        if (tid < 256) {
            float a[4];
#pragma unroll
            for (int g = 0; g < 4; ++g) {
                int o = g*4 + jl;
                float ssum = 0.f;
#pragma unroll
                for (int q = 0; q < 16; ++q) ssum += red[o*1024 + q*64 + gb];
                a[g] = ssum;
            }
            float gi = 1.f / (1.f + expf(-(xgi + a[0])));
            float gf = 1.f / (1.f + expf(-(xgf + a[1])));
            float gg = tanhf(xgg + a[2]);
            float go = 1.f / (1.f + expf(-(xgo + a[3])));
            c = gf * c + gi * gg;
            float h = go * tanhf(c);

            asm volatile("st.global.cg.f32 [%0], %1;"
                         :: "l"(&hT_d[(s&1)*HTBUF + col*64 + gb]), "f"(h) : "memory");
            g_xT[(size_t)(d*256 + col) * RR + te*64 + gb] = h;
        }
        __syncthreads();
        if (tid == 0) {
            unsigned v = base + (unsigned)(s + 1);
            asm volatile("st.release.gpu.global.u32 [%0], %1;" :: "l"(myflag), "r"(v) : "memory");
        }
    }
}

// =================================================================================
// feats from transposed input
// =================================================================================
__global__ void __launch_bounds__(128) feats_T(
    const float* __restrict__ wout,
    const float* __restrict__ bout)
{
    __shared__ float ws[512 * 8];
    int tid = threadIdx.x;
    int r = blockIdx.x * 128 + tid;

    for (int i = tid; i < 512 * 8; i += 128) {
        int e = i >> 3, k = i & 7;
        ws[i] = (k < 7) ? __ldg(&wout[k * 512 + e]) : 0.f;
    }
    __syncthreads();

    float acc[8];
#pragma unroll
    for (int k = 0; k < 8; k++) acc[k] = (k < 7) ? __ldg(&bout[k]) : 0.f;

#pragma unroll 4
    for (int e = 0; e < 512; ++e) {
        float x = __ldg(&g_xT[(size_t)e * RR + r]);
        float4 wa = *(const float4*)(ws + e*8);
        float4 wb = *(const float4*)(ws + e*8 + 4);
        acc[0] += x * wa.x; acc[1] += x * wa.y; acc[2] += x * wa.z; acc[3] += x * wa.w;
        acc[4] += x * wb.x; acc[5] += x * wb.y; acc[6] += x * wb.z;
    }
#pragma unroll
    for (int k = 0; k < 7; ++k) g_feats[r * KK + k] = acc[k];
}

// =================================================================================
// Viterbi: 448 threads = 64 batch x 7 next-tags
// =================================================================================
__global__ void viterbi_kernel(const float* __restrict__ trans,
                               void* out, int floatmode)
{
    __shared__ float vbuf[2][64][8];
    __shared__ float tr[7][7];

    int tid = threadIdx.x;
    if (tid < 49) tr[tid / 7][tid % 7] = trans[tid];
    int b  = tid & 63;
    int nx = tid >> 6;
    vbuf[0][b][nx] = (nx == START_TAG) ? 0.f : NEGV;
    __syncthreads();

    int p = 0;
    for (int t = 0; t < TT; ++t) {
        float best = vbuf[p][b][0] + tr[nx][0];
        int   bp   = 0;
#pragma unroll
        for (int pv = 1; pv < 7; ++pv) {
            float cnd = vbuf[p][b][pv] + tr[nx][pv];
            if (cnd > best) { best = cnd; bp = pv; }
        }
        vbuf[p ^ 1][b][nx] = best + g_feats[(t*BB + b) * KK + nx];
        g_bp[(t*BB + b) * 8 + nx] = (unsigned char)bp;
        __syncthreads();
        p ^= 1;
    }

    if (tid < 64) {
        float bestt = vbuf[p][tid][0] + tr[STOP_TAG][0];
        int   lastt = 0;
#pragma unroll
        for (int k2 = 1; k2 < 7; ++k2) {
            float cnd = vbuf[p][tid][k2] + tr[STOP_TAG][k2];
            if (cnd > bestt) { bestt = cnd; lastt = k2; }
        }
        int tag = lastt;
        if (floatmode) {
            float* fo = (float*)out;
            fo[RR + tid] = bestt;
            for (int t = TT - 1; t >= 0; --t) {
                fo[tid * TT + t] = (float)tag;
                tag = g_bp[(t*BB + tid) * 8 + tag];
            }
        } else {
            int* io = (int*)out;
            for (int t = TT - 1; t >= 0; --t) {
                io[tid * TT + t] = tag;
                tag = g_bp[(t*BB + tid) * 8 + tag];
            }
        }
    }
}

// =================================================================================
extern "C" void kernel_launch(void* const* d_in, const int* in_sizes, int n_in,
                              void* d_out, int out_size)
{
    const int*   sent  = (const int*)  d_in[0];
    const float* emb   = (const float*)d_in[1];
    const float* w_ih  = (const float*)d_in[2];
    const float* w_hh  = (const float*)d_in[3];
    const float* b_ih  = (const float*)d_in[4];
    const float* b_hh  = (const float*)d_in[5];
    const float* w_out = (const float*)d_in[6];
    const float* b_out = (const float*)d_in[7];
    const float* trans = (const float*)d_in[8];
    const float* h0    = (const float*)d_in[9];
    const float* c0    = (const float*)d_in[10];

    size_t lsmem = (size_t)(256*16 + 16*16*64) * sizeof(float);   // 80 KB
    cudaFuncSetAttribute(lstm_layer, cudaFuncAttributeMaxDynamicSharedMemorySize, (int)lsmem);

    dim3 ggrid(128, 16);            // x = n-tiles, y = m-tiles
    dim3 lgrid(64, 2);

    reset_flags<<<1, 128>>>();
    prep_wT<<<dim3(64, 16, 2), 256>>>(w_ih);
    gather_T<<<1024, 256>>>(sent, emb);

    prep_layer<<<lgrid, 256>>>(0, h0);
    gemm_db<<<ggrid, 256>>>(0, b_ih, b_hh);
    lstm_layer<<<lgrid, 512, lsmem>>>(0, w_hh, c0);

    prep_layer<<<lgrid, 256>>>(1, h0);
    gemm_db<<<ggrid, 256>>>(1, b_ih, b_hh);
    lstm_layer<<<lgrid, 512, lsmem>>>(1, w_hh, c0);

    feats_T<<<128, 128>>>(w_out, b_out);

    int floatmode = (out_size == RR + BB) ? 1 : 0;
    viterbi_kernel<<<1, 448>>>(trans, d_out, floatmode);
}